// round 16
// baseline (speedup 1.0000x reference)
#include <cuda_runtime.h>
#include <cuda_fp16.h>
#include <math.h>
#include <cstdint>

#define NQ       12
#define NLAYERS  5
#define DIM      4096
#define BSZ      4096

// ---------------- device scratch (no allocations allowed) ----------------
__device__ float2 g_psi0[DIM];
// Planar f16 features: A0 = re, A1 = im.  (a+b), (a-b) fragments derived
// in-register in the Gram kernel via HADD2/HSUB2 (elementwise fragments).
__device__ __align__(128) __half g_A0[(size_t)BSZ * DIM];
__device__ __align__(128) __half g_A1[(size_t)BSZ * DIM];

__device__ __forceinline__ float2 cmul(float2 a, float2 b) {
    return make_float2(a.x * b.x - a.y * b.y, a.x * b.y + a.y * b.x);
}
__device__ __forceinline__ float2 cadd(float2 a, float2 b) {
    return make_float2(a.x + b.x, a.y + b.y);
}

// Reference einsum 'st,blsr->bltr' applies U^T. T = U^T.
__device__ __forceinline__ void make_UT(float ph, float th, float lm,
                                        float2& T00, float2& T01,
                                        float2& T10, float2& T11) {
    float ct = cosf(0.5f * th), st = sinf(0.5f * th);
    float ap = 0.5f * (lm + ph), am = 0.5f * (lm - ph);
    float cap = cosf(ap), sap = sinf(ap);
    float cam = cosf(am), sam = sinf(am);
    float2 U00 = make_float2( ct * cap, -ct * sap);
    float2 U01 = make_float2(-st * cam,  st * sam);
    float2 U10 = make_float2( st * cam,  st * sam);
    float2 U11 = make_float2( ct * cap,  ct * sap);
    T00 = U00; T01 = U10; T10 = U01; T11 = U11;
}

// Fused 2-gate (adjacent qubits) register update of a 4-amplitude subspace.
__device__ __forceinline__ void fused2(float2& s00, float2& s01,
                                       float2& s10, float2& s11,
                                       float2 A00, float2 A01, float2 A10, float2 A11,
                                       float2 B00, float2 B01, float2 B10, float2 B11) {
    float2 t00 = cadd(cmul(A00, s00), cmul(A01, s10));
    float2 t10 = cadd(cmul(A10, s00), cmul(A11, s10));
    float2 t01 = cadd(cmul(A00, s01), cmul(A01, s11));
    float2 t11 = cadd(cmul(A10, s01), cmul(A11, s11));
    s00 = cadd(cmul(B00, t00), cmul(B01, t01));
    s01 = cadd(cmul(B10, t00), cmul(B11, t01));
    s10 = cadd(cmul(B00, t10), cmul(B01, t11));
    s11 = cadd(cmul(B10, t10), cmul(B11, t11));
}

// ---------------- Kernel A: data-independent prefix (layers 0..3) --------
__global__ void k_psi0(const float* __restrict__ params) {
    __shared__ float2 st[DIM];
    __shared__ float2 gates[48][4];
    int tid = threadIdx.x, nt = blockDim.x;  // nt = 1024

    if (tid < 48) {
        const float* p = params + tid * 3;
        float2 T00, T01, T10, T11;
        make_UT(p[0], p[1], p[2], T00, T01, T10, T11);
        gates[tid][0] = T00; gates[tid][1] = T01;
        gates[tid][2] = T10; gates[tid][3] = T11;
    }
    for (int i = tid; i < DIM; i += nt)
        st[i] = make_float2(i == 0 ? 1.0f : 0.0f, 0.0f);
    __syncthreads();

    for (int l = 0; l < NLAYERS - 1; l++) {
        for (int qp = 0; qp < NQ; qp += 2) {
            const float2* GA = gates[l * NQ + qp];
            const float2* GB = gates[l * NQ + qp + 1];
            int p1 = 10 - qp;
            int g = tid;
            int low = g & ((1 << p1) - 1);
            int i00 = ((g >> p1) << (p1 + 2)) | low;
            int i01 = i00 | (1 << p1);
            int i10 = i00 | (2 << p1);
            int i11 = i01 | (2 << p1);
            float2 s00 = st[i00], s01 = st[i01], s10 = st[i10], s11 = st[i11];
            fused2(s00, s01, s10, s11,
                   GA[0], GA[1], GA[2], GA[3],
                   GB[0], GB[1], GB[2], GB[3]);
            st[i00] = s00; st[i01] = s01; st[i10] = s10; st[i11] = s11;
            __syncthreads();
        }
        // composed CNOT permutation, single sweep
        {
            float2 tmp[4];
#pragma unroll
            for (int u = 0; u < 4; u++) {
                int idx = u * 1024 + tid;
                int j = idx;
#pragma unroll
                for (int q = NQ - 2; q >= 0; q--) {
                    int cb = 1 << (NQ - 1 - q);
                    int tb = 1 << (NQ - 2 - q);
                    if (j & cb) j ^= tb;
                }
                tmp[u] = st[j];
            }
            __syncthreads();
#pragma unroll
            for (int u = 0; u < 4; u++)
                st[u * 1024 + tid] = tmp[u];
            __syncthreads();
        }
    }
    for (int i = tid; i < DIM; i += nt) g_psi0[i] = st[i];
}

// ---------------- Kernel B: per-sample layer-4 gates + f16 features ------
__global__ void k_states(const float* __restrict__ X,
                         const float* __restrict__ params) {
    __shared__ float2 st[DIM];
    int i = blockIdx.x, tid = threadIdx.x, nt = blockDim.x;  // nt = 256
    for (int k = tid; k < DIM; k += nt) st[k] = g_psi0[k];
    __syncthreads();

    for (int qp = 0; qp < NQ; qp += 2) {
        float2 VA[4], VB[4];
#pragma unroll
        for (int s = 0; s < 2; s++) {
            int q = qp + s;
            const float* p = params + ((NLAYERS - 1) * NQ + q) * 3;
            float2 T00, T01, T10, T11;
            make_UT(p[0], p[1], p[2], T00, T01, T10, T11);
            float x = X[i * NQ + q];
            float gc = cosf(0.5f * x), gs = sinf(0.5f * x);
            float2* V = s ? VB : VA;
            V[0] = make_float2(gc * T00.x + gs * T10.x, gc * T00.y + gs * T10.y);
            V[1] = make_float2(gc * T01.x + gs * T11.x, gc * T01.y + gs * T11.y);
            V[2] = make_float2(-gs * T00.x + gc * T10.x, -gs * T00.y + gc * T10.y);
            V[3] = make_float2(-gs * T01.x + gc * T11.x, -gs * T01.y + gc * T11.y);
        }
        int p1 = 10 - qp;
        for (int g = tid; g < DIM / 4; g += nt) {
            int low = g & ((1 << p1) - 1);
            int i00 = ((g >> p1) << (p1 + 2)) | low;
            int i01 = i00 | (1 << p1);
            int i10 = i00 | (2 << p1);
            int i11 = i01 | (2 << p1);
            float2 s00 = st[i00], s01 = st[i01], s10 = st[i10], s11 = st[i11];
            fused2(s00, s01, s10, s11,
                   VA[0], VA[1], VA[2], VA[3],
                   VB[0], VB[1], VB[2], VB[3]);
            st[i00] = s00; st[i01] = s01; st[i10] = s10; st[i11] = s11;
        }
        __syncthreads();
    }

    size_t rowoff = (size_t)i * DIM;
    for (int k = tid; k < DIM; k += nt) {
        g_A0[rowoff + k] = __float2half_rn(st[k].x);
        g_A1[rowoff + k] = __float2half_rn(st[k].y);
    }
}

// =============  Kernel C: Gauss 3-mult f16 HMMA Gram, 64x128 tiles ========
// k1 = <(a+b)_i, a_j>,  k2 = <a_i, (a+b)_j>,  k3 = <b_i, (a-b)_j>
// re = k1 - k3 ; im = k1 - k2 ; K_out = re^2 + im^2.
// RATE EXPERIMENT: MMAs use f16 ACCUMULATORS (...f16.f16.f16.f16) — testing
// whether f32-acc HMMA is half-rate on sm_103a. f16 partials are promoted
// into fp32 mains every 4 kt (256 K-elements; rounding walk ~3e-5 abs).
#define KROWB     8192                  // bytes per operand row (4096 f16)
#define NKT       64                    // 8192B / 128B chunks
#define ITILE_B   8192                  // 64 rows x 128 bytes
#define JTILE_B   16384                 // 128 rows x 128 bytes
#define STAGE_B   (2 * ITILE_B + 2 * JTILE_B)   // 48KB
#define NSTAGE    3
#define GRAM_SMEM (NSTAGE * STAGE_B)    // 144KB
#define GRAM_THREADS 256
#define NBLK  1056                      // sum_{bj<32} (2*bj+2)

__device__ __forceinline__ uint32_t smem_u32(const void* p) {
    return (uint32_t)__cvta_generic_to_shared(p);
}
__device__ __forceinline__ void cp_async16(uint32_t dst, const void* src) {
    asm volatile("cp.async.cg.shared.global [%0], [%1], 16;" :: "r"(dst), "l"(src));
}
#define CP_COMMIT()  asm volatile("cp.async.commit_group;" ::: "memory")
#define CP_WAIT2()   asm volatile("cp.async.wait_group 2;" ::: "memory")
#define CP_WAIT0()   asm volatile("cp.async.wait_group 0;" ::: "memory")

__device__ __forceinline__ void ldsm4(uint32_t* r, uint32_t addr) {
    asm volatile("ldmatrix.sync.aligned.m8n8.x4.shared.b16 {%0,%1,%2,%3}, [%4];"
        : "=r"(r[0]), "=r"(r[1]), "=r"(r[2]), "=r"(r[3]) : "r"(addr));
}
// f16-accumulate HMMA: D (f16x2 x2) += A x B
__device__ __forceinline__ void mma_f16h(uint32_t* c, const uint32_t* a,
                                         uint32_t b0, uint32_t b1) {
    asm volatile(
        "mma.sync.aligned.m16n8k16.row.col.f16.f16.f16.f16 "
        "{%0,%1}, {%2,%3,%4,%5}, {%6,%7}, {%0,%1};"
        : "+r"(c[0]), "+r"(c[1])
        : "r"(a[0]), "r"(a[1]), "r"(a[2]), "r"(a[3]), "r"(b0), "r"(b1));
}
__device__ __forceinline__ uint32_t hadd2u(uint32_t a, uint32_t b) {
    uint32_t r; asm("add.rn.f16x2 %0, %1, %2;" : "=r"(r) : "r"(a), "r"(b)); return r;
}
__device__ __forceinline__ uint32_t hsub2u(uint32_t a, uint32_t b) {
    uint32_t r; asm("sub.rn.f16x2 %0, %1, %2;" : "=r"(r) : "r"(a), "r"(b)); return r;
}

__global__ void __launch_bounds__(GRAM_THREADS, 1)
k_gram_mma(float* __restrict__ K) {
    extern __shared__ __align__(1024) char smem[];
    const uint32_t smem_base = smem_u32(smem);
    const int tid  = threadIdx.x;
    const int wid  = tid >> 5;
    const int lane = tid & 31;
    const int wm = wid >> 2;            // 0..1  (32-row slab)
    const int wn = wid & 3;             // 0..3  (32-col slab)

    // tile mapping: bj = 128-col tile (0..31), bi = 64-row tile (0..2bj+1).
    int t = blockIdx.x;
    int bj = (int)((sqrtf(4.0f * (float)t + 1.0f) - 1.0f) * 0.5f);
    while ((bj + 1) * (bj + 2) <= t) bj++;
    while (bj * (bj + 1) > t) bj--;
    int bi = t - bj * (bj + 1);         // 0 .. 2bj+1
    int row0 = bi * 64;

    const char* gsrc[4];
    gsrc[0] = (const char*)g_A0 + (size_t)row0 * KROWB;      // i: a
    gsrc[1] = (const char*)g_A1 + (size_t)row0 * KROWB;      // i: b
    gsrc[2] = (const char*)g_A0 + (size_t)bj * 128 * KROWB;  // j: a
    gsrc[3] = (const char*)g_A1 + (size_t)bj * 128 * KROWB;  // j: b

    // ldmatrix per-thread geometry
    const int mat = lane >> 3, rl = lane & 7;
    const int rowA_base = wm * 32 + (mat & 1) * 8 + rl;   // + mt*16
    const uint32_t kselA = (uint32_t)((mat >> 1) * 16);
    const uint32_t xA = (uint32_t)(rowA_base & 7) << 4;
    const int rowB_base = wn * 32 + (mat >> 1) * 8 + rl;  // + np*16
    const uint32_t kselB = (uint32_t)((mat & 1) * 16);
    const uint32_t xB = (uint32_t)(rowB_base & 7) << 4;

    // fp32 main accumulators + f16 working accumulators
    float acc1[2][4][4], acc2[2][4][4], acc3[2][4][4];
    uint32_t h1[2][4][2], h2[2][4][2], h3[2][4][2];
#pragma unroll
    for (int mt = 0; mt < 2; mt++)
#pragma unroll
        for (int nt = 0; nt < 4; nt++) {
#pragma unroll
            for (int r = 0; r < 4; r++) {
                acc1[mt][nt][r] = 0.f; acc2[mt][nt][r] = 0.f; acc3[mt][nt][r] = 0.f;
            }
            h1[mt][nt][0] = 0; h1[mt][nt][1] = 0;
            h2[mt][nt][0] = 0; h2[mt][nt][1] = 0;
            h3[mt][nt][0] = 0; h3[mt][nt][1] = 0;
        }

    // ---------------- prologue: fill 3 stages --------------------------
#pragma unroll 1
    for (int pk = 0; pk < NSTAGE; pk++) {
        uint32_t sb = smem_base + pk * STAGE_B;
#pragma unroll
        for (int tt = 0; tt < 2; tt++) {            // i tiles (64 rows)
#pragma unroll
            for (int u = 0; u < 2; u++) {
                int p = u * 256 + tid;
                int rr = p >> 3, cc = p & 7;
                uint32_t dst = sb + tt * ITILE_B + (uint32_t)rr * 128 +
                               (((uint32_t)cc * 16) ^ (((uint32_t)rr & 7) << 4));
                cp_async16(dst, gsrc[tt] + (size_t)rr * KROWB + pk * 128 + cc * 16);
            }
        }
#pragma unroll
        for (int tt = 0; tt < 2; tt++) {            // j tiles (128 rows)
#pragma unroll
            for (int u = 0; u < 4; u++) {
                int p = u * 256 + tid;
                int rr = p >> 3, cc = p & 7;
                uint32_t dst = sb + 2 * ITILE_B + tt * JTILE_B + (uint32_t)rr * 128 +
                               (((uint32_t)cc * 16) ^ (((uint32_t)rr & 7) << 4));
                cp_async16(dst, gsrc[2 + tt] + (size_t)rr * KROWB + pk * 128 + cc * 16);
            }
        }
        CP_COMMIT();
    }

    // ---------------- main loop ----------------------------------------
    int stage = 0;
#pragma unroll 1
    for (int kt = 0; kt < NKT; kt++) {
        CP_WAIT2();
        __syncthreads();

        uint32_t sb = smem_base + stage * STAGE_B;
        uint32_t iA0 = sb                + (uint32_t)rowA_base * 128;
        uint32_t iA1 = sb + 1 * ITILE_B  + (uint32_t)rowA_base * 128;
        uint32_t jA0 = sb + 2 * ITILE_B                + (uint32_t)rowB_base * 128;
        uint32_t jA1 = sb + 2 * ITILE_B + 1 * JTILE_B  + (uint32_t)rowB_base * 128;

#pragma unroll
        for (int ks = 0; ks < 4; ks++) {
            uint32_t cA = ((uint32_t)(ks * 32) + kselA) ^ xA;
            uint32_t cB = ((uint32_t)(ks * 32) + kselB) ^ xB;

            uint32_t ai[2][4], bi_[2][4], aj[2][4], bjf[2][4];
#pragma unroll
            for (int mt = 0; mt < 2; mt++) {
                ldsm4(ai[mt],  iA0 + mt * 2048 + cA);
                ldsm4(bi_[mt], iA1 + mt * 2048 + cA);
            }
#pragma unroll
            for (int np = 0; np < 2; np++) {
                ldsm4(aj[np],  jA0 + np * 2048 + cB);
                ldsm4(bjf[np], jA1 + np * 2048 + cB);
            }
            uint32_t si[2][4], sj[2][4], dj[2][4];
#pragma unroll
            for (int mt = 0; mt < 2; mt++)
#pragma unroll
                for (int r = 0; r < 4; r++)
                    si[mt][r] = hadd2u(ai[mt][r], bi_[mt][r]);
#pragma unroll
            for (int np = 0; np < 2; np++)
#pragma unroll
                for (int r = 0; r < 4; r++) {
                    sj[np][r] = hadd2u(aj[np][r], bjf[np][r]);
                    dj[np][r] = hsub2u(aj[np][r], bjf[np][r]);
                }
            // 24 independent f16-acc MMAs
#pragma unroll
            for (int mt = 0; mt < 2; mt++)
#pragma unroll
                for (int np = 0; np < 2; np++)
#pragma unroll
                    for (int h = 0; h < 2; h++) {
                        int nt = np * 2 + h;
                        mma_f16h(h1[mt][nt], si[mt],
                                 aj[np][h * 2], aj[np][h * 2 + 1]);
                        mma_f16h(h2[mt][nt], ai[mt],
                                 sj[np][h * 2], sj[np][h * 2 + 1]);
                        mma_f16h(h3[mt][nt], bi_[mt],
                                 dj[np][h * 2], dj[np][h * 2 + 1]);
                    }
        }

        // promote f16 partials -> fp32 mains every 4 kt (256 K-elements)
        if ((kt & 3) == 3) {
#pragma unroll
            for (int mt = 0; mt < 2; mt++)
#pragma unroll
                for (int nt = 0; nt < 4; nt++) {
                    float2 lo, hi;
                    lo = __half22float2(*(__half2*)&h1[mt][nt][0]);
                    hi = __half22float2(*(__half2*)&h1[mt][nt][1]);
                    acc1[mt][nt][0] += lo.x; acc1[mt][nt][1] += lo.y;
                    acc1[mt][nt][2] += hi.x; acc1[mt][nt][3] += hi.y;
                    h1[mt][nt][0] = 0; h1[mt][nt][1] = 0;
                    lo = __half22float2(*(__half2*)&h2[mt][nt][0]);
                    hi = __half22float2(*(__half2*)&h2[mt][nt][1]);
                    acc2[mt][nt][0] += lo.x; acc2[mt][nt][1] += lo.y;
                    acc2[mt][nt][2] += hi.x; acc2[mt][nt][3] += hi.y;
                    h2[mt][nt][0] = 0; h2[mt][nt][1] = 0;
                    lo = __half22float2(*(__half2*)&h3[mt][nt][0]);
                    hi = __half22float2(*(__half2*)&h3[mt][nt][1]);
                    acc3[mt][nt][0] += lo.x; acc3[mt][nt][1] += lo.y;
                    acc3[mt][nt][2] += hi.x; acc3[mt][nt][3] += hi.y;
                    h3[mt][nt][0] = 0; h3[mt][nt][1] = 0;
                }
        }

        __syncthreads();

        int nk = kt + NSTAGE;
        if (nk < NKT) {
#pragma unroll
            for (int tt = 0; tt < 2; tt++) {
#pragma unroll
                for (int u = 0; u < 2; u++) {
                    int p = u * 256 + tid;
                    int rr = p >> 3, cc = p & 7;
                    uint32_t dst = sb + tt * ITILE_B + (uint32_t)rr * 128 +
                                   (((uint32_t)cc * 16) ^ (((uint32_t)rr & 7) << 4));
                    cp_async16(dst, gsrc[tt] + (size_t)rr * KROWB + nk * 128 + cc * 16);
                }
            }
#pragma unroll
            for (int tt = 0; tt < 2; tt++) {
#pragma unroll
                for (int u = 0; u < 4; u++) {
                    int p = u * 256 + tid;
                    int rr = p >> 3, cc = p & 7;
                    uint32_t dst = sb + 2 * ITILE_B + tt * JTILE_B + (uint32_t)rr * 128 +
                                   (((uint32_t)cc * 16) ^ (((uint32_t)rr & 7) << 4));
                    cp_async16(dst, gsrc[2 + tt] + (size_t)rr * KROWB + nk * 128 + cc * 16);
                }
            }
        }
        CP_COMMIT();

        stage = (stage == NSTAGE - 1) ? 0 : stage + 1;
    }

    // ------- epilogue: re = k1-k3, im = k1-k2, K = re^2 + im^2 ----------
    CP_WAIT0();
    __syncthreads();                      // smem tiles dead; reuse for transpose

    float* T = (float*)smem;              // [128 cols][68 pitch] local transpose
    const int r0 = row0 + wm * 32 + (lane >> 2);
    const int c0 = bj * 128 + wn * 32 + (lane & 3) * 2;
    const int rl0 = wm * 32 + (lane >> 2);
    const int cl0 = wn * 32 + (lane & 3) * 2;
#pragma unroll
    for (int mt = 0; mt < 2; mt++) {
#pragma unroll
        for (int nt = 0; nt < 4; nt++) {
            int row = r0 + mt * 16;
            int col = c0 + nt * 8;
            float v[4];
#pragma unroll
            for (int r = 0; r < 4; r++) {
                float re = acc1[mt][nt][r] - acc3[mt][nt][r];
                float im = acc1[mt][nt][r] - acc2[mt][nt][r];
                v[r] = re * re + im * im;
            }
            *(float2*)(K + (size_t)row * BSZ + col)       = make_float2(v[0], v[1]);
            *(float2*)(K + (size_t)(row + 8) * BSZ + col) = make_float2(v[2], v[3]);
            int rr = rl0 + mt * 16, cc = cl0 + nt * 8;
            T[cc * 68 + rr]           = v[0];
            T[(cc + 1) * 68 + rr]     = v[1];
            T[cc * 68 + rr + 8]       = v[2];
            T[(cc + 1) * 68 + rr + 8] = v[3];
        }
    }
    __syncthreads();
    {
        // coalesced mirror: row c of T -> K[(bj*128+c)][row0 ..]
        int c = tid >> 1, half = tid & 1;
        float4* dst = (float4*)(K + (size_t)(bj * 128 + c) * BSZ + row0 + half * 32);
        const float* src = T + c * 68 + half * 32;
#pragma unroll
        for (int i = 0; i < 8; i++)
            dst[i] = make_float4(src[4 * i], src[4 * i + 1],
                                 src[4 * i + 2], src[4 * i + 3]);
    }
}

// -------------------------------------------------------------------------
extern "C" void kernel_launch(void* const* d_in, const int* in_sizes, int n_in,
                              void* d_out, int out_size) {
    const float* X      = (const float*)d_in[0];   // (4096, 12)
    const float* params = (const float*)d_in[1];   // (5, 12, 3)
    float* K = (float*)d_out;                      // (4096, 4096)

    cudaFuncSetAttribute(k_gram_mma, cudaFuncAttributeMaxDynamicSharedMemorySize,
                         GRAM_SMEM);

    k_psi0    <<<1,    1024>>>(params);
    k_states  <<<BSZ,  256>>>(X, params);
    k_gram_mma<<<NBLK, GRAM_THREADS, GRAM_SMEM>>>(K);
}

// round 17
// speedup vs baseline: 1.1171x; 1.1171x over previous
#include <cuda_runtime.h>
#include <cuda_fp16.h>
#include <math.h>
#include <cstdint>

#define NQ       12
#define NLAYERS  5
#define DIM      4096
#define BSZ      4096

// ---------------- device scratch (no allocations allowed) ----------------
__device__ float2 g_psi0[DIM];
// Planar f16 features: A0 = re, A1 = im.  (a+b), (a-b) fragments derived
// in-register in the Gram kernel via HADD2/HSUB2 (elementwise fragments).
__device__ __align__(128) __half g_A0[(size_t)BSZ * DIM];
__device__ __align__(128) __half g_A1[(size_t)BSZ * DIM];

__device__ __forceinline__ float2 cmul(float2 a, float2 b) {
    return make_float2(a.x * b.x - a.y * b.y, a.x * b.y + a.y * b.x);
}
__device__ __forceinline__ float2 cadd(float2 a, float2 b) {
    return make_float2(a.x + b.x, a.y + b.y);
}

// Reference einsum 'st,blsr->bltr' applies U^T. T = U^T.
__device__ __forceinline__ void make_UT(float ph, float th, float lm,
                                        float2& T00, float2& T01,
                                        float2& T10, float2& T11) {
    float ct = cosf(0.5f * th), st = sinf(0.5f * th);
    float ap = 0.5f * (lm + ph), am = 0.5f * (lm - ph);
    float cap = cosf(ap), sap = sinf(ap);
    float cam = cosf(am), sam = sinf(am);
    float2 U00 = make_float2( ct * cap, -ct * sap);
    float2 U01 = make_float2(-st * cam,  st * sam);
    float2 U10 = make_float2( st * cam,  st * sam);
    float2 U11 = make_float2( ct * cap,  ct * sap);
    T00 = U00; T01 = U10; T10 = U01; T11 = U11;
}

// Fused 2-gate (adjacent qubits) register update of a 4-amplitude subspace.
__device__ __forceinline__ void fused2(float2& s00, float2& s01,
                                       float2& s10, float2& s11,
                                       float2 A00, float2 A01, float2 A10, float2 A11,
                                       float2 B00, float2 B01, float2 B10, float2 B11) {
    float2 t00 = cadd(cmul(A00, s00), cmul(A01, s10));
    float2 t10 = cadd(cmul(A10, s00), cmul(A11, s10));
    float2 t01 = cadd(cmul(A00, s01), cmul(A01, s11));
    float2 t11 = cadd(cmul(A10, s01), cmul(A11, s11));
    s00 = cadd(cmul(B00, t00), cmul(B01, t01));
    s01 = cadd(cmul(B10, t00), cmul(B11, t01));
    s10 = cadd(cmul(B00, t10), cmul(B01, t11));
    s11 = cadd(cmul(B10, t10), cmul(B11, t11));
}

// ---------------- Kernel A: data-independent prefix (layers 0..3) --------
__global__ void k_psi0(const float* __restrict__ params) {
    __shared__ float2 st[DIM];
    __shared__ float2 gates[48][4];
    int tid = threadIdx.x, nt = blockDim.x;  // nt = 1024

    if (tid < 48) {
        const float* p = params + tid * 3;
        float2 T00, T01, T10, T11;
        make_UT(p[0], p[1], p[2], T00, T01, T10, T11);
        gates[tid][0] = T00; gates[tid][1] = T01;
        gates[tid][2] = T10; gates[tid][3] = T11;
    }
    for (int i = tid; i < DIM; i += nt)
        st[i] = make_float2(i == 0 ? 1.0f : 0.0f, 0.0f);
    __syncthreads();

    for (int l = 0; l < NLAYERS - 1; l++) {
        for (int qp = 0; qp < NQ; qp += 2) {
            const float2* GA = gates[l * NQ + qp];
            const float2* GB = gates[l * NQ + qp + 1];
            int p1 = 10 - qp;
            int g = tid;
            int low = g & ((1 << p1) - 1);
            int i00 = ((g >> p1) << (p1 + 2)) | low;
            int i01 = i00 | (1 << p1);
            int i10 = i00 | (2 << p1);
            int i11 = i01 | (2 << p1);
            float2 s00 = st[i00], s01 = st[i01], s10 = st[i10], s11 = st[i11];
            fused2(s00, s01, s10, s11,
                   GA[0], GA[1], GA[2], GA[3],
                   GB[0], GB[1], GB[2], GB[3]);
            st[i00] = s00; st[i01] = s01; st[i10] = s10; st[i11] = s11;
            __syncthreads();
        }
        // composed CNOT permutation, single sweep
        {
            float2 tmp[4];
#pragma unroll
            for (int u = 0; u < 4; u++) {
                int idx = u * 1024 + tid;
                int j = idx;
#pragma unroll
                for (int q = NQ - 2; q >= 0; q--) {
                    int cb = 1 << (NQ - 1 - q);
                    int tb = 1 << (NQ - 2 - q);
                    if (j & cb) j ^= tb;
                }
                tmp[u] = st[j];
            }
            __syncthreads();
#pragma unroll
            for (int u = 0; u < 4; u++)
                st[u * 1024 + tid] = tmp[u];
            __syncthreads();
        }
    }
    for (int i = tid; i < DIM; i += nt) g_psi0[i] = st[i];
}

// ---------------- Kernel B: per-sample layer-4 gates + f16 features ------
__global__ void k_states(const float* __restrict__ X,
                         const float* __restrict__ params) {
    __shared__ float2 st[DIM];
    int i = blockIdx.x, tid = threadIdx.x, nt = blockDim.x;  // nt = 256
    for (int k = tid; k < DIM; k += nt) st[k] = g_psi0[k];
    __syncthreads();

    for (int qp = 0; qp < NQ; qp += 2) {
        float2 VA[4], VB[4];
#pragma unroll
        for (int s = 0; s < 2; s++) {
            int q = qp + s;
            const float* p = params + ((NLAYERS - 1) * NQ + q) * 3;
            float2 T00, T01, T10, T11;
            make_UT(p[0], p[1], p[2], T00, T01, T10, T11);
            float x = X[i * NQ + q];
            float gc = cosf(0.5f * x), gs = sinf(0.5f * x);
            float2* V = s ? VB : VA;
            V[0] = make_float2(gc * T00.x + gs * T10.x, gc * T00.y + gs * T10.y);
            V[1] = make_float2(gc * T01.x + gs * T11.x, gc * T01.y + gs * T11.y);
            V[2] = make_float2(-gs * T00.x + gc * T10.x, -gs * T00.y + gc * T10.y);
            V[3] = make_float2(-gs * T01.x + gc * T11.x, -gs * T01.y + gc * T11.y);
        }
        int p1 = 10 - qp;
        for (int g = tid; g < DIM / 4; g += nt) {
            int low = g & ((1 << p1) - 1);
            int i00 = ((g >> p1) << (p1 + 2)) | low;
            int i01 = i00 | (1 << p1);
            int i10 = i00 | (2 << p1);
            int i11 = i01 | (2 << p1);
            float2 s00 = st[i00], s01 = st[i01], s10 = st[i10], s11 = st[i11];
            fused2(s00, s01, s10, s11,
                   VA[0], VA[1], VA[2], VA[3],
                   VB[0], VB[1], VB[2], VB[3]);
            st[i00] = s00; st[i01] = s01; st[i10] = s10; st[i11] = s11;
        }
        __syncthreads();
    }

    size_t rowoff = (size_t)i * DIM;
    for (int k = tid; k < DIM; k += nt) {
        g_A0[rowoff + k] = __float2half_rn(st[k].x);
        g_A1[rowoff + k] = __float2half_rn(st[k].y);
    }
}

// =============  Kernel C: Gauss 3-mult f16 HMMA Gram  =====================
// k1 = <(a+b)_i, a_j>,  k2 = <a_i, (a+b)_j>,  k3 = <b_i, (a-b)_j>
// re = k1 - k3 ; im = k1 - k2 ; K_out = re^2 + im^2.
// 3-stage / SINGLE-SYNC pipeline: at iter kt the stage that held chunk kt-1
// is provably drained by the top barrier, so the refill for chunk kt+2
// (same physical stage, (kt+2)%3 == (kt-1)%3) is issued right after that
// one sync — the trailing barrier of the classic 2-stage scheme is gone.
#define KROWB     8192                  // bytes per operand row (4096 f16)
#define NKT       64                    // 8192B / 128B chunks
#define JTILE_B   16384                 // 128 rows x 128 bytes
#define NSTAGE    3
#define GRAM_SMEM (NSTAGE * (2 * JTILE_B + 2 * JTILE_B))   // 192KB (MT=4)
#define GRAM_THREADS 256
#define NFULL     456
#define NBLK      600                   // 456 full + 144 half

__device__ __forceinline__ uint32_t smem_u32(const void* p) {
    return (uint32_t)__cvta_generic_to_shared(p);
}
__device__ __forceinline__ void cp_async16(uint32_t dst, const void* src) {
    asm volatile("cp.async.cg.shared.global [%0], [%1], 16;" :: "r"(dst), "l"(src));
}
#define CP_COMMIT()  asm volatile("cp.async.commit_group;" ::: "memory")
#define CP_WAIT1()   asm volatile("cp.async.wait_group 1;" ::: "memory")
#define CP_WAIT0()   asm volatile("cp.async.wait_group 0;" ::: "memory")

__device__ __forceinline__ void ldsm4(uint32_t* r, uint32_t addr) {
    asm volatile("ldmatrix.sync.aligned.m8n8.x4.shared.b16 {%0,%1,%2,%3}, [%4];"
        : "=r"(r[0]), "=r"(r[1]), "=r"(r[2]), "=r"(r[3]) : "r"(addr));
}
__device__ __forceinline__ void mma_f16(float* c, const uint32_t* a,
                                        uint32_t b0, uint32_t b1) {
    asm volatile(
        "mma.sync.aligned.m16n8k16.row.col.f32.f16.f16.f32 "
        "{%0,%1,%2,%3}, {%4,%5,%6,%7}, {%8,%9}, {%0,%1,%2,%3};"
        : "+f"(c[0]), "+f"(c[1]), "+f"(c[2]), "+f"(c[3])
        : "r"(a[0]), "r"(a[1]), "r"(a[2]), "r"(a[3]), "r"(b0), "r"(b1));
}
__device__ __forceinline__ uint32_t hadd2u(uint32_t a, uint32_t b) {
    uint32_t r; asm("add.rn.f16x2 %0, %1, %2;" : "=r"(r) : "r"(a), "r"(b)); return r;
}
__device__ __forceinline__ uint32_t hsub2u(uint32_t a, uint32_t b) {
    uint32_t r; asm("sub.rn.f16x2 %0, %1, %2;" : "=r"(r) : "r"(a), "r"(b)); return r;
}

// MT = number of 16-row m-tiles per warp (4 -> 128-row tile, 2 -> 64-row tile)
template <int MT>
__device__ __forceinline__ void gram_body(float* __restrict__ K,
                                          char* smem, int row0, int bj) {
    const uint32_t smem_base = smem_u32(smem);
    const int tid  = threadIdx.x;
    const int wid  = tid >> 5;
    const int lane = tid & 31;
    const int wm = wid >> 2;            // 0..1
    const int wn = wid & 3;             // 0..3

    constexpr int ITB = MT * 32 * 128;          // i-tile bytes
    constexpr int STB = 2 * ITB + 2 * JTILE_B;  // stage bytes

    const char* gsrc[4];
    gsrc[0] = (const char*)g_A0 + (size_t)row0 * KROWB;      // i: a
    gsrc[1] = (const char*)g_A1 + (size_t)row0 * KROWB;      // i: b
    gsrc[2] = (const char*)g_A0 + (size_t)bj * 128 * KROWB;  // j: a
    gsrc[3] = (const char*)g_A1 + (size_t)bj * 128 * KROWB;  // j: b

    // ldmatrix per-thread geometry
    const int mat = lane >> 3, rl = lane & 7;
    const int rowA_base = wm * (MT * 16) + (mat & 1) * 8 + rl;   // + mt*16
    const uint32_t kselA = (uint32_t)((mat >> 1) * 16);
    const uint32_t xA = (uint32_t)(rowA_base & 7) << 4;
    const int rowB_base = wn * 32 + (mat >> 1) * 8 + rl;         // + np*16
    const uint32_t kselB = (uint32_t)((mat & 1) * 16);
    const uint32_t xB = (uint32_t)(rowB_base & 7) << 4;

    float acc1[MT][4][4], acc2[MT][4][4], acc3[MT][4][4];
#pragma unroll
    for (int mt = 0; mt < MT; mt++)
#pragma unroll
        for (int nt = 0; nt < 4; nt++)
#pragma unroll
            for (int r = 0; r < 4; r++) {
                acc1[mt][nt][r] = 0.f; acc2[mt][nt][r] = 0.f; acc3[mt][nt][r] = 0.f;
            }

    // helper lambda-free refill of chunk `nk` into stage (nk % NSTAGE)
    // (expanded inline twice below to keep everything compile-time)

    // ---------------- prologue: fill stages 0,1 (chunks 0,1) -----------
#pragma unroll 1
    for (int pk = 0; pk < 2; pk++) {
        uint32_t sb = smem_base + pk * STB;
#pragma unroll
        for (int tt = 0; tt < 2; tt++) {            // i tiles (MT*32 rows)
#pragma unroll
            for (int u = 0; u < MT; u++) {
                int p = u * 256 + tid;
                int rr = p >> 3, cc = p & 7;
                uint32_t dst = sb + tt * ITB + (uint32_t)rr * 128 +
                               (((uint32_t)cc * 16) ^ (((uint32_t)rr & 7) << 4));
                cp_async16(dst, gsrc[tt] + (size_t)rr * KROWB + pk * 128 + cc * 16);
            }
        }
#pragma unroll
        for (int tt = 0; tt < 2; tt++) {            // j tiles (128 rows)
#pragma unroll
            for (int u = 0; u < 4; u++) {
                int p = u * 256 + tid;
                int rr = p >> 3, cc = p & 7;
                uint32_t dst = sb + 2 * ITB + tt * JTILE_B + (uint32_t)rr * 128 +
                               (((uint32_t)cc * 16) ^ (((uint32_t)rr & 7) << 4));
                cp_async16(dst, gsrc[2 + tt] + (size_t)rr * KROWB + pk * 128 + cc * 16);
            }
        }
        CP_COMMIT();
    }

    // ---------------- main loop (ONE sync per kt) ----------------------
    int stage = 0;          // stage holding chunk kt
    int rstage = 2;         // stage to refill (chunk kt+2)
#pragma unroll 1
    for (int kt = 0; kt < NKT; kt++) {
        CP_WAIT1();                 // chunk kt resident (kt+1 may be in flight)
        __syncthreads();            // all warps done with chunk kt-1's stage

        // refill chunk kt+2 into stage (kt+2)%3 == (kt-1)%3 (drained above)
        int nk = kt + 2;
        if (nk < NKT) {
            uint32_t sbf = smem_base + rstage * STB;
#pragma unroll
            for (int tt = 0; tt < 2; tt++) {
#pragma unroll
                for (int u = 0; u < MT; u++) {
                    int p = u * 256 + tid;
                    int rr = p >> 3, cc = p & 7;
                    uint32_t dst = sbf + tt * ITB + (uint32_t)rr * 128 +
                                   (((uint32_t)cc * 16) ^ (((uint32_t)rr & 7) << 4));
                    cp_async16(dst, gsrc[tt] + (size_t)rr * KROWB + nk * 128 + cc * 16);
                }
            }
#pragma unroll
            for (int tt = 0; tt < 2; tt++) {
#pragma unroll
                for (int u = 0; u < 4; u++) {
                    int p = u * 256 + tid;
                    int rr = p >> 3, cc = p & 7;
                    uint32_t dst = sbf + 2 * ITB + tt * JTILE_B + (uint32_t)rr * 128 +
                                   (((uint32_t)cc * 16) ^ (((uint32_t)rr & 7) << 4));
                    cp_async16(dst, gsrc[2 + tt] + (size_t)rr * KROWB + nk * 128 + cc * 16);
                }
            }
        }
        CP_COMMIT();                // always commit (empty group keeps counts aligned)

        uint32_t sb = smem_base + stage * STB;
        uint32_t iA0 = sb           + (uint32_t)rowA_base * 128;
        uint32_t iA1 = sb + 1 * ITB + (uint32_t)rowA_base * 128;
        uint32_t jA0 = sb + 2 * ITB               + (uint32_t)rowB_base * 128;
        uint32_t jA1 = sb + 2 * ITB + 1 * JTILE_B + (uint32_t)rowB_base * 128;

#pragma unroll
        for (int ks = 0; ks < 4; ks++) {
            uint32_t cA = ((uint32_t)(ks * 32) + kselA) ^ xA;
            uint32_t cB = ((uint32_t)(ks * 32) + kselB) ^ xB;

            // B-side: load a_j, b_j; derive s_j = a+b, d_j = a-b
            uint32_t aj[2][4], sj[2][4], dj[2][4];
#pragma unroll
            for (int np = 0; np < 2; np++) {
                uint32_t bjf[4];
                ldsm4(aj[np], jA0 + np * 2048 + cB);
                ldsm4(bjf,    jA1 + np * 2048 + cB);
#pragma unroll
                for (int r = 0; r < 4; r++) {
                    sj[np][r] = hadd2u(aj[np][r], bjf[r]);
                    dj[np][r] = hsub2u(aj[np][r], bjf[r]);
                }
            }

            // A-side per mt: ldsm-first chains (acc2/acc3) before the
            // HADD2-dependent chain (acc1) to hide the FADD latency.
#pragma unroll
            for (int mt = 0; mt < MT; mt++) {
                uint32_t ai[4], bi_[4], si[4];
                ldsm4(ai,  iA0 + mt * 2048 + cA);
                ldsm4(bi_, iA1 + mt * 2048 + cA);
#pragma unroll
                for (int r = 0; r < 4; r++) si[r] = hadd2u(ai[r], bi_[r]);
#pragma unroll
                for (int np = 0; np < 2; np++)
#pragma unroll
                    for (int h = 0; h < 2; h++)
                        mma_f16(acc2[mt][np * 2 + h], ai,
                                sj[np][h * 2], sj[np][h * 2 + 1]);
#pragma unroll
                for (int np = 0; np < 2; np++)
#pragma unroll
                    for (int h = 0; h < 2; h++)
                        mma_f16(acc3[mt][np * 2 + h], bi_,
                                dj[np][h * 2], dj[np][h * 2 + 1]);
#pragma unroll
                for (int np = 0; np < 2; np++)
#pragma unroll
                    for (int h = 0; h < 2; h++)
                        mma_f16(acc1[mt][np * 2 + h], si,
                                aj[np][h * 2], aj[np][h * 2 + 1]);
            }
        }

        stage  = (stage  == NSTAGE - 1) ? 0 : stage + 1;
        rstage = (rstage == NSTAGE - 1) ? 0 : rstage + 1;
    }

    // ------- epilogue: re = k1-k3, im = k1-k2, K = re^2 + im^2 ----------
    CP_WAIT0();
    __syncthreads();                      // smem tiles dead; reuse for transpose

    constexpr int P = MT * 32 + 4;        // transpose pitch (floats)
    float* T = (float*)smem;              // [128 cols][P pitch]
    const int r0 = row0 + wm * (MT * 16) + (lane >> 2);
    const int c0 = bj * 128 + wn * 32 + (lane & 3) * 2;
    const int rl0 = wm * (MT * 16) + (lane >> 2);
    const int cl0 = wn * 32 + (lane & 3) * 2;
#pragma unroll
    for (int mt = 0; mt < MT; mt++) {
#pragma unroll
        for (int nt = 0; nt < 4; nt++) {
            int row = r0 + mt * 16;
            int col = c0 + nt * 8;
            float v[4];
#pragma unroll
            for (int r = 0; r < 4; r++) {
                float re = acc1[mt][nt][r] - acc3[mt][nt][r];
                float im = acc1[mt][nt][r] - acc2[mt][nt][r];
                v[r] = re * re + im * im;
            }
            *(float2*)(K + (size_t)row * BSZ + col)       = make_float2(v[0], v[1]);
            *(float2*)(K + (size_t)(row + 8) * BSZ + col) = make_float2(v[2], v[3]);
            int rr = rl0 + mt * 16, cc = cl0 + nt * 8;
            T[cc * P + rr]           = v[0];
            T[(cc + 1) * P + rr]     = v[1];
            T[cc * P + rr + 8]       = v[2];
            T[(cc + 1) * P + rr + 8] = v[3];
        }
    }
    __syncthreads();
    {
        // coalesced mirror: row c of T -> K[(bj*128+c)][row0 ..]
        int c = tid >> 1, half = tid & 1;
        float4* dst = (float4*)(K + (size_t)(bj * 128 + c) * BSZ + row0 + half * (MT * 16));
        const float* src = T + c * P + half * (MT * 16);
#pragma unroll
        for (int i = 0; i < MT * 4; i++)
            dst[i] = make_float4(src[4 * i], src[4 * i + 1],
                                 src[4 * i + 2], src[4 * i + 3]);
    }
}

__global__ void __launch_bounds__(GRAM_THREADS, 1)
k_gram_mma(float* __restrict__ K) {
    extern __shared__ __align__(1024) char smem[];

    int t = blockIdx.x;
    int ftile, rh;
    if (t < NFULL) { ftile = t; rh = -1; }
    else { int ht = t - NFULL; ftile = NFULL + (ht >> 1); rh = ht & 1; }

    // triangular decode: ftile -> (bi <= bj)
    int bj = (int)((sqrtf(8.0f * (float)ftile + 1.0f) - 1.0f) * 0.5f);
    while ((bj + 1) * (bj + 2) / 2 <= ftile) bj++;
    while (bj * (bj + 1) / 2 > ftile) bj--;
    int bi = ftile - bj * (bj + 1) / 2;

    if (rh < 0) gram_body<4>(K, smem, bi * 128, bj);
    else        gram_body<2>(K, smem, bi * 128 + rh * 64, bj);
}

// -------------------------------------------------------------------------
extern "C" void kernel_launch(void* const* d_in, const int* in_sizes, int n_in,
                              void* d_out, int out_size) {
    const float* X      = (const float*)d_in[0];   // (4096, 12)
    const float* params = (const float*)d_in[1];   // (5, 12, 3)
    float* K = (float*)d_out;                      // (4096, 4096)

    cudaFuncSetAttribute(k_gram_mma, cudaFuncAttributeMaxDynamicSharedMemorySize,
                         GRAM_SMEM);

    k_psi0    <<<1,    1024>>>(params);
    k_states  <<<BSZ,  256>>>(X, params);
    k_gram_mma<<<NBLK, GRAM_THREADS, GRAM_SMEM>>>(K);
}